// round 11
// baseline (speedup 1.0000x reference)
#include <cuda_runtime.h>
#include <cuda_fp16.h>
#include <cstdint>
#include <cstddef>

// ============================================================================
// Fused LSTM cell, sm_103: fp16 mma.m16n8k16 + ldmatrix.
//  R11: R10 mbarrier pipeline + (1) XOR-folded swizzle addresses (1 LOP3 per
//  LDSM instead of full sw() recompute), (2) cross-iteration fragment preload
//  (ks=3 MMAs issue before next-stage full-wait, so try_wait overlaps a full
//  MMA train), (3) affine producer addressing.
// ============================================================================

#define BATCH 16384
#define HID   512
#define KD    1024
#define BK    64
#define NST   3
#define NITER (KD / BK)            // 16
#define STAGE_BYTES 32768          // A 128x64 fp16 (16KB) + B (16KB)
#define PIPE_OFF    98304
#define DYN_BYTES   (98304 + 64)

__device__ __align__(256) __half g_A16[(size_t)BATCH * KD];     // 32 MB
__device__ __align__(256) __half g_W16[(size_t)2048  * KD];     // 4 MB

// ---------------------------------------------------------------------------
__device__ __forceinline__ uint32_t s2u(const void* p) {
    uint32_t a;
    asm("{ .reg .u64 t; cvta.to.shared.u64 t, %1; cvt.u32.u64 %0, t; }"
        : "=r"(a) : "l"(p));
    return a;
}
__device__ __forceinline__ void cp16(uint32_t dst, const void* src) {
    asm volatile("cp.async.cg.shared.global [%0], [%1], 16;"
                 :: "r"(dst), "l"(src));
}
__device__ __forceinline__ void ldm_x4(uint32_t* d, uint32_t a) {
    asm volatile("ldmatrix.sync.aligned.m8n8.x4.shared.b16 {%0,%1,%2,%3}, [%4];"
                 : "=r"(d[0]), "=r"(d[1]), "=r"(d[2]), "=r"(d[3]) : "r"(a));
}
__device__ __forceinline__ void mma16816(float* d, const uint32_t* a,
                                         const uint32_t* b) {
    asm volatile(
        "mma.sync.aligned.m16n8k16.row.col.f32.f16.f16.f32 "
        "{%0,%1,%2,%3}, {%4,%5,%6,%7}, {%8,%9}, {%0,%1,%2,%3};"
        : "+f"(d[0]), "+f"(d[1]), "+f"(d[2]), "+f"(d[3])
        : "r"(a[0]), "r"(a[1]), "r"(a[2]), "r"(a[3]), "r"(b[0]), "r"(b[1]));
}
__device__ __forceinline__ void bar_init(uint32_t bar, uint32_t cnt) {
    asm volatile("mbarrier.init.shared.b64 [%0], %1;" :: "r"(bar), "r"(cnt)
                 : "memory");
}
__device__ __forceinline__ void bar_wait(uint32_t bar, uint32_t parity) {
    asm volatile(
        "{\n\t.reg .pred P;\n\t"
        "WL%=:\n\t"
        "mbarrier.try_wait.parity.shared.b64 P, [%0], %1;\n\t"
        "@P bra WD%=;\n\t"
        "bra WL%=;\n\t"
        "WD%=:\n\t}"
        :: "r"(bar), "r"(parity) : "memory");
}
__device__ __forceinline__ void bar_arrive(uint32_t bar) {
    asm volatile("mbarrier.arrive.shared.b64 _, [%0];" :: "r"(bar) : "memory");
}
__device__ __forceinline__ void cp_arrive_noinc(uint32_t bar) {
    asm volatile("cp.async.mbarrier.arrive.noinc.shared.b64 [%0];"
                 :: "r"(bar) : "memory");
}
__device__ __forceinline__ float sigmoid_f(float x) {
    return 1.0f / (1.0f + __expf(-x));
}
__device__ __forceinline__ float tanh_f(float x) {
    float e = __expf(2.0f * x);
    return 1.0f - 2.0f / (e + 1.0f);
}

// ---------------------------------------------------------------------------
// merged pre-pass: blocks [0,4096) convert A, blocks [4096,4608) convert W.
__global__ void __launch_bounds__(256) convAW(const float* __restrict__ ph,
                                              const float* __restrict__ xin,
                                              const float* __restrict__ Wi,
                                              const float* __restrict__ Wf,
                                              const float* __restrict__ Wo,
                                              const float* __restrict__ Wg) {
    if (blockIdx.x < 4096) {
        const size_t idx = (size_t)blockIdx.x * 256 + threadIdx.x;  // 1M thr
        #pragma unroll
        for (int j = 0; j < 4; ++j) {
            const size_t i = idx + (size_t)j * 1048576;             // 4M groups
            const int row = (int)(i >> 8);
            const int col = (int)(i & 255) * 4;
            const float* s = (col < 512) ? (ph + (size_t)row * 512 + col)
                                         : (xin + (size_t)row * 512 + (col - 512));
            const float4 v = *(const float4*)s;
            __half2 h0 = __floats2half2_rn(v.x, v.y);
            __half2 h1 = __floats2half2_rn(v.z, v.w);
            uint2 u;
            u.x = *reinterpret_cast<uint32_t*>(&h0);
            u.y = *reinterpret_cast<uint32_t*>(&h1);
            *(uint2*)(g_A16 + i * 4) = u;
        }
    } else {
        const size_t idx = (size_t)(blockIdx.x - 4096) * 256 + threadIdx.x;
        #pragma unroll
        for (int j = 0; j < 4; ++j) {
            const size_t i = idx + (size_t)j * 131072;              // 512K groups
            const int orow = (int)(i >> 8);
            const int col  = (int)(i & 255) * 4;
            const int ht = orow >> 7, r = orow & 127;
            // gate-interleaved: gate = bits[3:4], h = b6*16 + b5*8 + b[0:2]
            const int gate = (r >> 3) & 3;
            const int h    = ((r >> 6) << 4) + (((r >> 5) & 1) << 3) + (r & 7);
            const int hrow = ht * 32 + h;
            const float* W = (gate == 0) ? Wi : (gate == 1) ? Wf
                           : (gate == 2) ? Wo : Wg;
            const float4 v = *(const float4*)(W + (size_t)hrow * KD + col);
            __half2 h0 = __floats2half2_rn(v.x, v.y);
            __half2 h1 = __floats2half2_rn(v.z, v.w);
            uint2 u;
            u.x = *reinterpret_cast<uint32_t*>(&h0);
            u.y = *reinterpret_cast<uint32_t*>(&h1);
            *(uint2*)(g_W16 + i * 4) = u;
        }
    }
}

// ---------------------------------------------------------------------------
__global__ void __launch_bounds__(256, 2)
lstm_fp16_gemm(const float* __restrict__ prev_c,
               const float* __restrict__ bi, const float* __restrict__ bf,
               const float* __restrict__ bo, const float* __restrict__ bg,
               float* __restrict__ h_out, float* __restrict__ c_out)
{
    extern __shared__ char smc[];
    const uint32_t sb = s2u(smc);
    const uint32_t FULLB  = sb + PIPE_OFF;
    const uint32_t EMPTYB = sb + PIPE_OFF + 24;

    const int tid = threadIdx.x;
    const int wid = tid >> 5;
    const int lid = tid & 31;
    const int hb  = blockIdx.x;            // 16 h-tiles
    const int mb  = blockIdx.y;            // 128 m-tiles
    const int wm  = wid >> 1;              // 0..3
    const int wn  = wid & 1;               // 0..1

    if (tid == 0) {
        #pragma unroll
        for (int s = 0; s < NST; ++s) {
            bar_init(FULLB  + 8 * s, 256);
            bar_init(EMPTYB + 8 * s, 256);
        }
    }
    __syncthreads();

    // ---- producer mapping: affine smem offsets ------------------------------
    const int cr = tid >> 3;               // 0..31
    const int cc = tid & 7;                // chunk 0..7
    // (cr+32i)&7 == cr&7, so the xor term is i-invariant
    const uint32_t off_cp = (uint32_t)(cr * 128 + ((cc ^ (cr & 7)) << 4));
    const __half* gA = g_A16 + (size_t)(mb * 128) * KD + cc * 8;
    const __half* gB = g_W16 + (size_t)(hb * 128) * KD + cc * 8;

    auto produce = [&](int kt) {
        const int s2 = kt % NST;
        const uint32_t so = sb + (uint32_t)s2 * STAGE_BYTES + off_cp;
        const int kcol = kt * BK;
        #pragma unroll
        for (int i = 0; i < 4; ++i) {
            const int r = cr + 32 * i;
            cp16(so + i * 4096,         gA + (size_t)r * KD + kcol);
            cp16(so + 16384 + i * 4096, gB + (size_t)r * KD + kcol);
        }
        cp_arrive_noinc(FULLB + 8 * s2);
    };

    produce(0);
    produce(1);

    // ---- accumulators pre-loaded with biases --------------------------------
    float acc[2][8][4];
    {
        const int hq = hb * 32 + wn * 16 + (lid & 3) * 2;
        #pragma unroll
        for (int ni = 0; ni < 8; ++ni) {
            const int gate = ni & 3;
            const int h = hq + ((ni >> 2) << 3);
            const float* bp = (gate == 0) ? bi : (gate == 1) ? bf
                            : (gate == 2) ? bo : bg;
            const float b0 = __ldg(&bp[h]);
            const float b1 = __ldg(&bp[h + 1]);
            #pragma unroll
            for (int mi = 0; mi < 2; ++mi) {
                acc[mi][ni][0] = b0; acc[mi][ni][1] = b1;
                acc[mi][ni][2] = b0; acc[mi][ni][3] = b1;
            }
        }
    }

    // ---- XOR-folded ldmatrix base offsets ------------------------------------
    // sw(r, ks*2 + c) = r*128 + (((ks*2+c) ^ (r&7))<<4)
    //                 = [r*128 + ((c^(r&7))<<4)] ^ (ks<<5)    (disjoint bits)
    const int a_r = (lid & 15);
    const int a_c = (lid >> 4);
    const int b_r = ((lid >> 4) << 3) + (lid & 7);
    const int b_c = ((lid >> 3) & 1);
    uint32_t offA[2], offB[4];
    #pragma unroll
    for (int mi = 0; mi < 2; ++mi) {
        const int r = wm * 32 + mi * 16 + a_r;
        offA[mi] = (uint32_t)(r * 128 + ((a_c ^ (r & 7)) << 4));
    }
    #pragma unroll
    for (int n2 = 0; n2 < 4; ++n2) {
        const int r = wn * 64 + n2 * 16 + b_r;
        offB[n2] = (uint32_t)(16384 + r * 128 + ((b_c ^ (r & 7)) << 4));
    }

    uint32_t a[2][2][4], b[2][8][2];       // double-buffered fragments

    auto preload = [&](int buf, uint32_t stage_base, int ks) {
        const uint32_t x = (uint32_t)(ks << 5);
        #pragma unroll
        for (int mi = 0; mi < 2; ++mi)
            ldm_x4(a[buf][mi], stage_base + (offA[mi] ^ x));
        #pragma unroll
        for (int n2 = 0; n2 < 4; ++n2) {
            uint32_t t4[4];
            ldm_x4(t4, stage_base + (offB[n2] ^ x));
            b[buf][n2 * 2][0] = t4[0]; b[buf][n2 * 2][1] = t4[1];
            b[buf][n2 * 2 + 1][0] = t4[2]; b[buf][n2 * 2 + 1][1] = t4[3];
        }
    };

    // prologue: stage 0 fragments
    bar_wait(FULLB + 0, 0);
    preload(0, sb, 0);

    #pragma unroll 1
    for (int it = 0; it < NITER; ++it) {
        const int s = it % NST;
        const uint32_t smA = sb + (uint32_t)s * STAGE_BYTES;

        // producer for stage it+2
        if (it + 2 < NITER) {
            const int i2 = it + 2;
            if (i2 >= NST)
                bar_wait(EMPTYB + 8 * (i2 % NST), ((i2 / NST) - 1) & 1);
            produce(i2);
        }

        #pragma unroll
        for (int ks = 0; ks < 4; ++ks) {
            const int cur = ks & 1, nxt = cur ^ 1;
            if (ks < 3) {
                preload(nxt, smA, ks + 1);
                #pragma unroll
                for (int mi = 0; mi < 2; ++mi)
                    #pragma unroll
                    for (int ni = 0; ni < 8; ++ni)
                        mma16816(acc[mi][ni], a[cur][mi], b[cur][ni]);
            } else {
                // fill the tensor pipe first, THEN wait for the next stage:
                // try_wait (~90cyc) overlaps 16 in-flight MMAs.
                #pragma unroll
                for (int mi = 0; mi < 2; ++mi)
                    #pragma unroll
                    for (int ni = 0; ni < 8; ++ni)
                        mma16816(acc[mi][ni], a[cur][mi], b[cur][ni]);
                if (it + 1 < NITER) {
                    const int s1 = (it + 1) % NST;
                    bar_wait(FULLB + 8 * s1, ((it + 1) / NST) & 1);
                    preload(nxt, sb + (uint32_t)s1 * STAGE_BYTES, 0);
                }
            }
        }
        bar_arrive(EMPTYB + 8 * s);
    }

    // ---- register-local epilogue --------------------------------------------
    #pragma unroll
    for (int mi = 0; mi < 2; ++mi) {
        const int r_base = mb * 128 + wm * 32 + mi * 16 + (lid >> 2);
        #pragma unroll
        for (int ho = 0; ho < 2; ++ho) {
            const int hg = hb * 32 + wn * 16 + ho * 8 + (lid & 3) * 2;
            #pragma unroll
            for (int pr = 0; pr < 2; ++pr) {
                const int r = r_base + pr * 8;
                const size_t off = (size_t)r * HID + hg;
                const float2 pc = *(const float2*)(prev_c + off);
                const int q0 = pr * 2, q1 = pr * 2 + 1;
                const float i0 = sigmoid_f(acc[mi][ho * 4 + 0][q0]);
                const float f0 = sigmoid_f(acc[mi][ho * 4 + 1][q0]);
                const float o0 = sigmoid_f(acc[mi][ho * 4 + 2][q0]);
                const float g0 = tanh_f   (acc[mi][ho * 4 + 3][q0]);
                const float i1 = sigmoid_f(acc[mi][ho * 4 + 0][q1]);
                const float f1 = sigmoid_f(acc[mi][ho * 4 + 1][q1]);
                const float o1 = sigmoid_f(acc[mi][ho * 4 + 2][q1]);
                const float g1 = tanh_f   (acc[mi][ho * 4 + 3][q1]);
                const float c0 = f0 * pc.x + i0 * g0;
                const float c1 = f1 * pc.y + i1 * g1;
                *(float2*)(h_out + off) = make_float2(tanh_f(c0) * o0,
                                                      tanh_f(c1) * o1);
                *(float2*)(c_out + off) = make_float2(c0, c1);
            }
        }
    }
}

// ---------------------------------------------------------------------------
extern "C" void kernel_launch(void* const* d_in, const int* in_sizes, int n_in,
                              void* d_out, int out_size) {
    const float* input_ = (const float*)d_in[0];
    const float* prev_h = (const float*)d_in[1];
    const float* prev_c = (const float*)d_in[2];
    const float* W_i = (const float*)d_in[3];  const float* b_i = (const float*)d_in[4];
    const float* W_f = (const float*)d_in[5];  const float* b_f = (const float*)d_in[6];
    const float* W_g = (const float*)d_in[7];  const float* b_g = (const float*)d_in[8];
    const float* W_o = (const float*)d_in[9];  const float* b_o = (const float*)d_in[10];

    float* h_out = (float*)d_out;
    float* c_out = h_out + (size_t)BATCH * HID;

    convAW<<<4608, 256>>>(prev_h, input_, W_i, W_f, W_o, W_g);

    cudaFuncSetAttribute(lstm_fp16_gemm,
                         cudaFuncAttributeMaxDynamicSharedMemorySize, DYN_BYTES);
    dim3 grid(16, 128);
    lstm_fp16_gemm<<<grid, 256, DYN_BYTES>>>(prev_c, b_i, b_f, b_o, b_g,
                                             h_out, c_out);
}